// round 9
// baseline (speedup 1.0000x reference)
#include <cuda_runtime.h>
#include <cuda_bf16.h>
#include <math.h>
#include <cfloat>
#include <cstdint>

// ===========================================================================
// MIL-NCE head: s = (v @ t^T)/0.1, N=4096, T=4, D=256 (NT=16384)
// Outputs: [loss, recall1, recall5, recall10, avg_rank]
//
// Fully fused: no S materialization.
//  K0 init   : rank counters <- 0
//  K1 split  : fp32 -> 2x bf16 splits of v and t
//  K2 pos    : exact fp32 positives p[i][t] = (v_i . t_{4i+t}) * 10
//  K3 gemm   : mma.sync bf16 3-product GEMM (256 thr, 8 warps, 4m x 2n);
//              REGISTER-LEVEL fragment double-buffering: LDSM for k16+1
//              issues into the alternate frag set while k16's HMMAs run.
//              Epilogue: rank counts (self-excluded) + per-warp-tile
//              row/col (max, sumexp) partials.
//  K4 rowfin : warp-per-row deterministic merge -> loss + metrics
//  K5 reduce : deterministic means
// ===========================================================================

namespace {
constexpr int N  = 4096;
constexpr int T  = 4;
constexpr int NT = 16384;
constexpr int D  = 256;
constexpr float SCALE   = 10.0f;
constexpr float LSE_CUT = 30.0f;

constexpr int BM = 128, BN = 128;
constexpr int KC = 64;                      // K chunk: 64 bf16 = 128B rows (SW128)
constexpr int NCHUNK = D / KC;              // 4
constexpr int CTILE = NT / BN;              // 128 col tiles
constexpr int RTILE = N / BM;               // 32 row tiles
constexpr int CSLOT = CTILE * 2;            // 256 row-LSE slots (per 64-col warp tile)
constexpr int RSLOT = RTILE * 4;            // 128 col-LSE slots (per 32-row warp tile)

constexpr int NA = N * D;
constexpr int NB = NT * D;

constexpr int TILE_B    = BM * KC * 2;      // 16384 bytes per split tile
constexpr int STAGE_B   = 4 * TILE_B;       // A0,A1,B0,B1 = 65536
constexpr int GEMM_SMEM = 2 * STAGE_B;      // 131072 (double buffer)
}

// ------------------------- device scratch ---------------------------------
__device__ __nv_bfloat16  g_As[2][NA];
__device__ __nv_bfloat16  g_Bs[2][NB];
__device__ float4         g_pos[N];              // positives (scaled)
__device__ int            g_cnt[N][T];
__device__ float2         g_rowMS[N][CSLOT];     // (max, sumexp) row slots
__device__ float2         g_colMS[NT][RSLOT];    // (max, sumexp) col slots
__device__ float          g_rowout[N][5];

// ------------------------- helpers ----------------------------------------
__device__ __forceinline__ uint32_t smem_u32(const void* p) {
    uint32_t a;
    asm("{ .reg .u64 t; cvta.to.shared.u64 t, %1; cvt.u32.u64 %0, t; }" : "=r"(a) : "l"(p));
    return a;
}
__device__ __forceinline__ uint32_t sw128(uint32_t b) { return b ^ ((b >> 3) & 0x70); }

__device__ __forceinline__ void ldsm4(uint32_t* r, uint32_t addr) {
    asm volatile("ldmatrix.sync.aligned.m8n8.x4.shared.b16 {%0,%1,%2,%3}, [%4];"
        : "=r"(r[0]), "=r"(r[1]), "=r"(r[2]), "=r"(r[3]) : "r"(addr));
}
__device__ __forceinline__ void mma_bf16(float* d, const uint32_t* a, uint32_t b0, uint32_t b1) {
    asm volatile("mma.sync.aligned.m16n8k16.row.col.f32.bf16.bf16.f32 "
        "{%0,%1,%2,%3}, {%4,%5,%6,%7}, {%8,%9}, {%0,%1,%2,%3};"
        : "+f"(d[0]), "+f"(d[1]), "+f"(d[2]), "+f"(d[3])
        : "r"(a[0]), "r"(a[1]), "r"(a[2]), "r"(a[3]), "r"(b0), "r"(b1));
}
__device__ __forceinline__ void cp16(uint32_t dst, const void* src) {
    asm volatile("cp.async.cg.shared.global [%0], [%1], 16;" :: "r"(dst), "l"(src));
}
#define CP_COMMIT() asm volatile("cp.async.commit_group;" ::: "memory")
#define CP_WAIT(n)  asm volatile("cp.async.wait_group %0;" :: "n"(n) : "memory")

// (m,s) logsumexp-pair merge, deterministic given fixed call order
__device__ __forceinline__ void msmerge(float& m, float& s, float m2, float s2) {
    float M = fmaxf(m, m2);
    s = s * expf(m - M) + s2 * expf(m2 - M);
    m = M;
}

// ===========================================================================
// K0: init rank counters
__global__ void init_kernel() {
    int i = blockIdx.x * 256 + threadIdx.x;
    if (i < NT) g_cnt[i >> 2][i & 3] = 0;
}

// ===========================================================================
// K1: 2-way bf16 split
__global__ __launch_bounds__(256)
void split_kernel(const float* __restrict__ v, const float* __restrict__ t) {
    int i = blockIdx.x * 256 + threadIdx.x;
    if (i >= NA + NB) return;
    float a = (i < NA) ? v[i] : t[i - NA];
    __nv_bfloat16 h0 = __float2bfloat16(a);
    float r1 = a - __bfloat162float(h0);
    __nv_bfloat16 h1 = __float2bfloat16(r1);
    if (i < NA) { g_As[0][i] = h0; g_As[1][i] = h1; }
    else { int j = i - NA; g_Bs[0][j] = h0; g_Bs[1][j] = h1; }
}

// ===========================================================================
// K2: exact fp32 positives. One warp per (i,t) pair.
__global__ __launch_bounds__(256)
void pos_kernel(const float* __restrict__ v, const float* __restrict__ t) {
    int w = (blockIdx.x * 256 + threadIdx.x) >> 5;   // 0..16383
    int lane = threadIdx.x & 31;
    int i = w >> 2, tt = w & 3;
    const float4* vp = reinterpret_cast<const float4*>(v + (size_t)i * D);
    const float4* tp = reinterpret_cast<const float4*>(t + (size_t)w * D);
    float s = 0.f;
    #pragma unroll
    for (int k = 0; k < 2; k++) {
        float4 a = vp[lane + 32 * k];
        float4 b = tp[lane + 32 * k];
        s += a.x * b.x + a.y * b.y + a.z * b.z + a.w * b.w;
    }
    #pragma unroll
    for (int off = 16; off; off >>= 1)
        s += __shfl_xor_sync(0xffffffffu, s, off);
    if (lane == 0) reinterpret_cast<float*>(&g_pos[i])[tt] = s * SCALE;
}

// ===========================================================================
// K3: HMMA GEMM + fused epilogue (no S output).
// Block tile 128x128, 8 warps as 4(m) x 2(n): warp tile 32x64.
// Fragment registers are double-buffered across k16 steps.
__global__ __launch_bounds__(256, 1)
void gemm_mma() {
    extern __shared__ char smem[];
    __shared__ float4 spos[BM];               // positives for this CTA's rows
    const uint32_t sb = smem_u32(smem);
    const int tid = threadIdx.x, lane = tid & 31, wid = tid >> 5;
    const int wm = wid >> 1, wn = wid & 1;
    const int bn = blockIdx.x, bm = blockIdx.y;

    if (tid < BM) spos[tid] = g_pos[bm * BM + tid];

    // ldmatrix per-lane addressing (SW128, 128B rows)
    const int a_r    = lane & 15;
    const int a_koff = (lane >> 4) * 16;
    const int b_r    = (lane & 7) + ((lane & 16) >> 1);
    const int b_koff = (lane & 8) << 1;
    const uint32_t a_xm = (uint32_t)(a_r & 7) << 4;
    const uint32_t b_xm = (uint32_t)(b_r & 7) << 4;

    uint32_t a_rowb[2], b_rowb[4];
    #pragma unroll
    for (int mi = 0; mi < 2; mi++) a_rowb[mi] = (uint32_t)(wm * 32 + mi * 16 + a_r) * 128;
    #pragma unroll
    for (int p = 0; p < 4; p++)    b_rowb[p]  = (uint32_t)(wn * 64 + p * 16 + b_r) * 128;

    float acc[2][8][4];
    #pragma unroll
    for (int mi = 0; mi < 2; mi++)
        #pragma unroll
        for (int nf = 0; nf < 8; nf++)
            #pragma unroll
            for (int q = 0; q < 4; q++) acc[mi][nf][q] = 0.f;

    // ping-pong fragment register sets
    uint32_t afr[2][2][2][4];   // [buf][split][mi]
    uint32_t bfr[2][2][4][4];   // [buf][split][p]

    auto prefetch = [&](int stage, int kc) {
        const int k0 = kc * KC;
        #pragma unroll
        for (int i = 0; i < 16; i++) {
            int g = i * 256 + tid;
            int s = g >> 10;
            int idx = g & 1023;
            int r = idx >> 3, b = idx & 7;
            const __nv_bfloat16* src =
                (s < 2) ? (g_As[s]     + (size_t)(bm * BM + r) * D + k0 + b * 8)
                        : (g_Bs[s - 2] + (size_t)(bn * BN + r) * D + k0 + b * 8);
            cp16(sb + stage * STAGE_B + s * TILE_B + sw128(r * 128 + b * 16), src);
        }
    };

    prefetch(0, 0);
    CP_COMMIT();

    for (int kc = 0; kc < NCHUNK; kc++) {
        if (kc < NCHUNK - 1) { prefetch((kc + 1) & 1, kc + 1); CP_COMMIT(); CP_WAIT(1); }
        else { CP_WAIT(0); }
        __syncthreads();

        const uint32_t base = sb + (kc & 1) * STAGE_B;

        // load fragments for k16 = 0 into buffer 0
        #pragma unroll
        for (int s2 = 0; s2 < 2; s2++) {
            #pragma unroll
            for (int mi = 0; mi < 2; mi++)
                ldsm4(afr[0][s2][mi], base + s2 * TILE_B + a_rowb[mi] + ((0 + a_koff) ^ a_xm));
            #pragma unroll
            for (int p = 0; p < 4; p++)
                ldsm4(bfr[0][s2][p], base + (2 + s2) * TILE_B + b_rowb[p] + ((0 + b_koff) ^ b_xm));
        }

        #pragma unroll
        for (int k16 = 0; k16 < 4; k16++) {
            const int cur = k16 & 1;
            // prefetch fragments for k16+1 into the other buffer (independent
            // of the MMAs below -> covers LDSM latency)
            if (k16 < 3) {
                const uint32_t kb = (k16 + 1) * 32;
                #pragma unroll
                for (int s2 = 0; s2 < 2; s2++) {
                    #pragma unroll
                    for (int mi = 0; mi < 2; mi++)
                        ldsm4(afr[cur ^ 1][s2][mi],
                              base + s2 * TILE_B + a_rowb[mi] + ((kb + a_koff) ^ a_xm));
                    #pragma unroll
                    for (int p = 0; p < 4; p++)
                        ldsm4(bfr[cur ^ 1][s2][p],
                              base + (2 + s2) * TILE_B + b_rowb[p] + ((kb + b_koff) ^ b_xm));
                }
            }

            // product-major MMA stream on the current buffer
            #pragma unroll
            for (int pr = 0; pr < 3; pr++) {
                const int sA = (pr == 2) ? 1 : 0;   // products (0,0),(0,1),(1,0)
                const int sB = (pr == 1) ? 1 : 0;
                #pragma unroll
                for (int mi = 0; mi < 2; mi++)
                    #pragma unroll
                    for (int nf = 0; nf < 8; nf++) {
                        const uint32_t* bp = &bfr[cur][sB][nf >> 1][(nf & 1) * 2];
                        mma_bf16(acc[mi][nf], afr[cur][sA][mi], bp[0], bp[1]);
                    }
            }
        }
        __syncthreads();
    }

    // ======== fused epilogue ========
    #pragma unroll
    for (int mi = 0; mi < 2; mi++)
        #pragma unroll
        for (int nf = 0; nf < 8; nf++)
            #pragma unroll
            for (int q = 0; q < 4; q++) acc[mi][nf][q] *= SCALE;

    const int qr = lane >> 2;
    const int qc = (lane & 3) * 2;
    const int gcolbase = bn * BN + wn * 64;

    // --- per-row: rank counts (self-excluded) + row-tile (max, sumexp) ---
    #pragma unroll
    for (int mi = 0; mi < 2; mi++)
        #pragma unroll
        for (int h = 0; h < 2; h++) {
            const int lrow = wm * 32 + mi * 16 + h * 8 + qr;
            const int grow = bm * BM + lrow;
            const float4 pv = spos[lrow];
            int c0 = 0, c1 = 0, c2 = 0, c3 = 0;
            float m = -FLT_MAX;
            #pragma unroll
            for (int nf = 0; nf < 8; nf++)
                #pragma unroll
                for (int b = 0; b < 2; b++) {
                    const float x = acc[mi][nf][2 * h + b];
                    const int gcol = gcolbase + nf * 8 + qc + b;
                    const bool sv = (gcol >> 2) == grow;
                    c0 += (x > pv.x) && !(sv && (gcol & 3) == 0);
                    c1 += (x > pv.y) && !(sv && (gcol & 3) == 1);
                    c2 += (x > pv.z) && !(sv && (gcol & 3) == 2);
                    c3 += (x > pv.w) && !(sv && (gcol & 3) == 3);
                    m = fmaxf(m, x);
                }
            #pragma unroll
            for (int off = 1; off <= 2; off <<= 1) {
                c0 += __shfl_xor_sync(0xffffffffu, c0, off);
                c1 += __shfl_xor_sync(0xffffffffu, c1, off);
                c2 += __shfl_xor_sync(0xffffffffu, c2, off);
                c3 += __shfl_xor_sync(0xffffffffu, c3, off);
                m = fmaxf(m, __shfl_xor_sync(0xffffffffu, m, off));
            }
            const float thr = m - LSE_CUT;
            float s = 0.f;
            #pragma unroll
            for (int nf = 0; nf < 8; nf++)
                #pragma unroll
                for (int b = 0; b < 2; b++) {
                    const float x = acc[mi][nf][2 * h + b];
                    if (x > thr) s += expf(x - m);
                }
            s += __shfl_xor_sync(0xffffffffu, s, 1);
            s += __shfl_xor_sync(0xffffffffu, s, 2);
            if ((lane & 3) == 0) {
                atomicAdd(&g_cnt[grow][0], c0);
                atomicAdd(&g_cnt[grow][1], c1);
                atomicAdd(&g_cnt[grow][2], c2);
                atomicAdd(&g_cnt[grow][3], c3);
                g_rowMS[grow][bn * 2 + wn] = make_float2(m, s);
            }
        }

    // --- per-col: col-tile (max, sumexp) ---
    #pragma unroll
    for (int nf = 0; nf < 8; nf++)
        #pragma unroll
        for (int b = 0; b < 2; b++) {
            float m = -FLT_MAX;
            #pragma unroll
            for (int mi = 0; mi < 2; mi++)
                #pragma unroll
                for (int h = 0; h < 2; h++)
                    m = fmaxf(m, acc[mi][nf][2 * h + b]);
            #pragma unroll
            for (int off = 4; off <= 16; off <<= 1)
                m = fmaxf(m, __shfl_xor_sync(0xffffffffu, m, off));
            const float thr = m - LSE_CUT;
            float s = 0.f;
            #pragma unroll
            for (int mi = 0; mi < 2; mi++)
                #pragma unroll
                for (int h = 0; h < 2; h++) {
                    const float x = acc[mi][nf][2 * h + b];
                    if (x > thr) s += expf(x - m);
                }
            #pragma unroll
            for (int off = 4; off <= 16; off <<= 1)
                s += __shfl_xor_sync(0xffffffffu, s, off);
            if (lane < 4)
                g_colMS[gcolbase + nf * 8 + qc + b][bm * 4 + wm] = make_float2(m, s);
        }
}

// ===========================================================================
// K4: warp-per-row deterministic merge -> loss + metrics per row
__global__ __launch_bounds__(256)
void rowfin_kernel() {
    const int i = blockIdx.x * 8 + (threadIdx.x >> 5);   // row
    const int lane = threadIdx.x & 31;

    float2 e = g_rowMS[i][lane];
    float m = e.x, s = e.y;
    for (int k = lane + 32; k < CSLOT; k += 32) {
        float2 f = g_rowMS[i][k];
        msmerge(m, s, f.x, f.y);
    }
    #pragma unroll
    for (int t = 0; t < 4; t++)
        for (int k = lane; k < RSLOT; k += 32) {
            float2 f = g_colMS[i * 4 + t][k];
            msmerge(m, s, f.x, f.y);
        }
    #pragma unroll
    for (int off = 16; off; off >>= 1) {
        float m2 = __shfl_xor_sync(0xffffffffu, m, off);
        float s2 = __shfl_xor_sync(0xffffffffu, s, off);
        msmerge(m, s, m2, s2);
    }

    if (lane == 0) {
        float denom = m + logf(s);
        float4 p = g_pos[i];
        float pm = fmaxf(fmaxf(p.x, p.y), fmaxf(p.z, p.w));
        float nom = pm + logf(expf(p.x - pm) + expf(p.y - pm) +
                              expf(p.z - pm) + expf(p.w - pm));
        float r1 = 0.f, r5 = 0.f, r10 = 0.f, ar = 0.f;
        #pragma unroll
        for (int t = 0; t < 4; t++) {
            int rk = g_cnt[i][t];
            r1  += (rk < 1);
            r5  += (rk < 5);
            r10 += (rk < 10);
            ar  += (float)rk;
        }
        g_rowout[i][0] = denom - nom;
        g_rowout[i][1] = r1  * 0.25f;
        g_rowout[i][2] = r5  * 0.25f;
        g_rowout[i][3] = r10 * 0.25f;
        g_rowout[i][4] = ar  * 0.25f;
    }
}

// ===========================================================================
// K5: deterministic means
__global__ __launch_bounds__(256)
void final_kernel(float* __restrict__ out) {
    __shared__ double sacc[5][256];
    int tid = threadIdx.x;
    double a[5] = {0, 0, 0, 0, 0};
    for (int i = tid; i < N; i += 256)
        #pragma unroll
        for (int q = 0; q < 5; q++) a[q] += (double)g_rowout[i][q];
    #pragma unroll
    for (int q = 0; q < 5; q++) sacc[q][tid] = a[q];
    __syncthreads();
    for (int off = 128; off > 0; off >>= 1) {
        if (tid < off)
            #pragma unroll
            for (int q = 0; q < 5; q++) sacc[q][tid] += sacc[q][tid + off];
        __syncthreads();
    }
    if (tid == 0)
        #pragma unroll
        for (int q = 0; q < 5; q++) out[q] = (float)(sacc[q][0] / (double)N);
}

// ===========================================================================
extern "C" void kernel_launch(void* const* d_in, const int* in_sizes, int n_in,
                              void* d_out, int out_size) {
    const float* v = (const float*)d_in[0];   // [4096, 256]
    const float* t = (const float*)d_in[1];   // [16384, 256]
    (void)in_sizes; (void)n_in; (void)out_size;

    static int attr_done = 0;
    if (!attr_done) {
        cudaFuncSetAttribute(gemm_mma, cudaFuncAttributeMaxDynamicSharedMemorySize, GEMM_SMEM);
        attr_done = 1;
    }

    init_kernel<<<NT / 256, 256>>>();
    split_kernel<<<(NA + NB + 255) / 256, 256>>>(v, t);
    pos_kernel<<<(NT * 32) / 256, 256>>>(v, t);
    gemm_mma<<<dim3(CTILE, RTILE), 256, GEMM_SMEM>>>();
    rowfin_kernel<<<N / 8, 256>>>();
    final_kernel<<<1, 256>>>((float*)d_out);
}

// round 13
// speedup vs baseline: 1.1311x; 1.1311x over previous
#include <cuda_runtime.h>
#include <cuda_bf16.h>
#include <math.h>
#include <cfloat>
#include <cstdint>

// ===========================================================================
// MIL-NCE head: s = (v @ t^T)/0.1, N=4096, T=4, D=256 (NT=16384)
// Outputs: [loss, recall1, recall5, recall10, avg_rank]
//
// R4 architecture (fastest measured) + high-occupancy stats:
//  K0 init   : rmax/cmax <- -inf, cnt <- 0
//  K1 split  : fp32 -> 2x bf16 splits of v and t
//  K2 gemm   : mma.sync bf16 3-product GEMM, cp.async double-buffered,
//              S -> scratch, exact row/col maxes (deterministic atomicMax)
//  K3 stats  : smem-staged 64x128 block pass (5 CTA/SM): rank counts,
//              row/col sumexp partials (threshold-gated exp)
//  K4 rowfin : per-row LSE combine + metrics
//  K5 reduce : deterministic means
// ===========================================================================

namespace {
constexpr int N  = 4096;
constexpr int T  = 4;
constexpr int NT = 16384;
constexpr int D  = 256;
constexpr float SCALE   = 10.0f;
constexpr float LSE_CUT = 30.0f;

constexpr int BM = 128, BN = 128;
constexpr int KC = 64;                      // K chunk: 64 bf16 = 128B rows (SW128)
constexpr int NCHUNK = D / KC;              // 4
constexpr int CTILE = NT / BN;              // 128
constexpr int RT64  = N / 64;               // 64 stats row-tiles

constexpr int NA = N * D;
constexpr int NB = NT * D;

constexpr int TILE_B    = BM * KC * 2;      // 16384 bytes per split tile
constexpr int STAGE_B   = 4 * TILE_B;       // A0,A1,B0,B1 = 65536
constexpr int GEMM_SMEM = 2 * STAGE_B;      // 131072 (double buffer)

constexpr int SPAD = 132;                   // stats tile row pitch (words)
}

// ------------------------- device scratch ---------------------------------
__device__ float          g_S[(size_t)N * NT];   // 256 MB
__device__ __nv_bfloat16  g_As[2][NA];
__device__ __nv_bfloat16  g_Bs[2][NB];
__device__ int            g_rmax[N];
__device__ int            g_cmax[NT];
__device__ int            g_cnt[N][T];
__device__ float          g_cpart[RT64][NT];     // col partial sumexp per 64-row tile
__device__ float          g_rspart[CTILE][N];    // row partial sumexp per col-tile
__device__ float          g_rowout[N][5];

// ------------------------- helpers ----------------------------------------
__device__ __forceinline__ int enc_f(float f) {
    int i = __float_as_int(f);
    return i >= 0 ? i : i ^ 0x7fffffff;
}
__device__ __forceinline__ float dec_f(int i) {
    return __int_as_float(i >= 0 ? i : i ^ 0x7fffffff);
}
__device__ __forceinline__ uint32_t smem_u32(const void* p) {
    uint32_t a;
    asm("{ .reg .u64 t; cvta.to.shared.u64 t, %1; cvt.u32.u64 %0, t; }" : "=r"(a) : "l"(p));
    return a;
}
__device__ __forceinline__ uint32_t sw128(uint32_t b) { return b ^ ((b >> 3) & 0x70); }

__device__ __forceinline__ void ldsm4(uint32_t* r, uint32_t addr) {
    asm volatile("ldmatrix.sync.aligned.m8n8.x4.shared.b16 {%0,%1,%2,%3}, [%4];"
        : "=r"(r[0]), "=r"(r[1]), "=r"(r[2]), "=r"(r[3]) : "r"(addr));
}
__device__ __forceinline__ void mma_bf16(float* d, const uint32_t* a, uint32_t b0, uint32_t b1) {
    asm volatile("mma.sync.aligned.m16n8k16.row.col.f32.bf16.bf16.f32 "
        "{%0,%1,%2,%3}, {%4,%5,%6,%7}, {%8,%9}, {%0,%1,%2,%3};"
        : "+f"(d[0]), "+f"(d[1]), "+f"(d[2]), "+f"(d[3])
        : "r"(a[0]), "r"(a[1]), "r"(a[2]), "r"(a[3]), "r"(b0), "r"(b1));
}
__device__ __forceinline__ void cp16(uint32_t dst, const void* src) {
    asm volatile("cp.async.cg.shared.global [%0], [%1], 16;" :: "r"(dst), "l"(src));
}
#define CP_COMMIT() asm volatile("cp.async.commit_group;" ::: "memory")
#define CP_WAIT(n)  asm volatile("cp.async.wait_group %0;" :: "n"(n) : "memory")

// ===========================================================================
// K0: init
__global__ void init_kernel() {
    int i = blockIdx.x * 256 + threadIdx.x;
    if (i < N)  g_rmax[i] = (int)0x80000000;
    if (i < NT) {
        g_cmax[i] = (int)0x80000000;
        g_cnt[i >> 2][i & 3] = 0;
    }
}

// ===========================================================================
// K1: 2-way bf16 split
__global__ __launch_bounds__(256)
void split_kernel(const float* __restrict__ v, const float* __restrict__ t) {
    int i = blockIdx.x * 256 + threadIdx.x;
    if (i >= NA + NB) return;
    float a = (i < NA) ? v[i] : t[i - NA];
    __nv_bfloat16 h0 = __float2bfloat16(a);
    float r1 = a - __bfloat162float(h0);
    __nv_bfloat16 h1 = __float2bfloat16(r1);
    if (i < NA) { g_As[0][i] = h0; g_As[1][i] = h1; }
    else { int j = i - NA; g_Bs[0][j] = h0; g_Bs[1][j] = h1; }
}

// ===========================================================================
// K2: HMMA GEMM (R4-identical). Block tile 128x128, 8 warps 4m x 2n.
__global__ __launch_bounds__(256, 1)
void gemm_mma() {
    extern __shared__ char smem[];
    const uint32_t sb = smem_u32(smem);
    const int tid = threadIdx.x, lane = tid & 31, wid = tid >> 5;
    const int wm = wid >> 1, wn = wid & 1;
    const int bn = blockIdx.x, bm = blockIdx.y;

    const int a_r    = lane & 15;
    const int a_koff = (lane >> 4) * 16;
    const int b_r    = (lane & 7) + ((lane & 16) >> 1);
    const int b_koff = (lane & 8) << 1;
    const uint32_t a_xm = (uint32_t)(a_r & 7) << 4;
    const uint32_t b_xm = (uint32_t)(b_r & 7) << 4;

    uint32_t a_rowb[2], b_rowb[4];
    #pragma unroll
    for (int mi = 0; mi < 2; mi++) a_rowb[mi] = (uint32_t)(wm * 32 + mi * 16 + a_r) * 128;
    #pragma unroll
    for (int p = 0; p < 4; p++)    b_rowb[p]  = (uint32_t)(wn * 64 + p * 16 + b_r) * 128;

    float acc[2][8][4];
    #pragma unroll
    for (int mi = 0; mi < 2; mi++)
        #pragma unroll
        for (int nf = 0; nf < 8; nf++)
            #pragma unroll
            for (int q = 0; q < 4; q++) acc[mi][nf][q] = 0.f;

    auto prefetch = [&](int stage, int kc) {
        const int k0 = kc * KC;
        #pragma unroll
        for (int i = 0; i < 16; i++) {
            int g = i * 256 + tid;
            int s = g >> 10;
            int idx = g & 1023;
            int r = idx >> 3, b = idx & 7;
            const __nv_bfloat16* src =
                (s < 2) ? (g_As[s]     + (size_t)(bm * BM + r) * D + k0 + b * 8)
                        : (g_Bs[s - 2] + (size_t)(bn * BN + r) * D + k0 + b * 8);
            cp16(sb + stage * STAGE_B + s * TILE_B + sw128(r * 128 + b * 16), src);
        }
    };

    prefetch(0, 0);
    CP_COMMIT();

    for (int kc = 0; kc < NCHUNK; kc++) {
        if (kc < NCHUNK - 1) { prefetch((kc + 1) & 1, kc + 1); CP_COMMIT(); CP_WAIT(1); }
        else { CP_WAIT(0); }
        __syncthreads();

        const uint32_t base = sb + (kc & 1) * STAGE_B;
        #pragma unroll
        for (int k16 = 0; k16 < 4; k16++) {
            const uint32_t kb = k16 * 32;
            uint32_t afr[2][4];
            #pragma unroll
            for (int s2 = 0; s2 < 2; s2++)
                #pragma unroll
                for (int mi = 0; mi < 2; mi++)
                    ;
            uint32_t af[2][2][4];   // [split][mi]
            #pragma unroll
            for (int s2 = 0; s2 < 2; s2++)
                #pragma unroll
                for (int mi = 0; mi < 2; mi++)
                    ldsm4(af[s2][mi], base + s2 * TILE_B + a_rowb[mi] + ((kb + a_koff) ^ a_xm));
            uint32_t bf[2][4][4];   // [split][p]
            #pragma unroll
            for (int s2 = 0; s2 < 2; s2++)
                #pragma unroll
                for (int p = 0; p < 4; p++)
                    ldsm4(bf[s2][p], base + (2 + s2) * TILE_B + b_rowb[p] + ((kb + b_koff) ^ b_xm));
            (void)afr;

            #pragma unroll
            for (int mi = 0; mi < 2; mi++)
                #pragma unroll
                for (int nf = 0; nf < 8; nf++) {
                    const uint32_t* bp0 = &bf[0][nf >> 1][(nf & 1) * 2];
                    const uint32_t* bp1 = &bf[1][nf >> 1][(nf & 1) * 2];
                    mma_bf16(acc[mi][nf], af[0][mi], bp0[0], bp0[1]);
                    mma_bf16(acc[mi][nf], af[0][mi], bp1[0], bp1[1]);
                    mma_bf16(acc[mi][nf], af[1][mi], bp0[0], bp0[1]);
                }
        }
        __syncthreads();
    }

    // ---- epilogue: scale, store S, exact row/col maxes ----
    #pragma unroll
    for (int mi = 0; mi < 2; mi++)
        #pragma unroll
        for (int nf = 0; nf < 8; nf++)
            #pragma unroll
            for (int q = 0; q < 4; q++) acc[mi][nf][q] *= SCALE;

    const int qr = lane >> 2;
    const int qc = (lane & 3) * 2;

    #pragma unroll
    for (int mi = 0; mi < 2; mi++)
        #pragma unroll
        for (int h = 0; h < 2; h++) {
            int row = bm * BM + wm * 32 + mi * 16 + h * 8 + qr;
            float* dst = g_S + (size_t)row * NT + (size_t)bn * BN + wn * 64 + qc;
            #pragma unroll
            for (int nf = 0; nf < 8; nf++)
                *reinterpret_cast<float2*>(dst + nf * 8) =
                    make_float2(acc[mi][nf][2 * h], acc[mi][nf][2 * h + 1]);
        }

    #pragma unroll
    for (int mi = 0; mi < 2; mi++)
        #pragma unroll
        for (int h = 0; h < 2; h++) {
            float m = -FLT_MAX;
            #pragma unroll
            for (int nf = 0; nf < 8; nf++)
                m = fmaxf(m, fmaxf(acc[mi][nf][2 * h], acc[mi][nf][2 * h + 1]));
            m = fmaxf(m, __shfl_xor_sync(0xffffffffu, m, 1));
            m = fmaxf(m, __shfl_xor_sync(0xffffffffu, m, 2));
            if ((lane & 3) == 0)
                atomicMax(&g_rmax[bm * BM + wm * 32 + mi * 16 + h * 8 + qr], enc_f(m));
        }

    #pragma unroll
    for (int nf = 0; nf < 8; nf++) {
        float m0 = -FLT_MAX, m1 = -FLT_MAX;
        #pragma unroll
        for (int mi = 0; mi < 2; mi++) {
            m0 = fmaxf(m0, fmaxf(acc[mi][nf][0], acc[mi][nf][2]));
            m1 = fmaxf(m1, fmaxf(acc[mi][nf][1], acc[mi][nf][3]));
        }
        #pragma unroll
        for (int off = 4; off < 32; off <<= 1) {
            m0 = fmaxf(m0, __shfl_xor_sync(0xffffffffu, m0, off));
            m1 = fmaxf(m1, __shfl_xor_sync(0xffffffffu, m1, off));
        }
        if (lane < 4) {
            int col = bn * BN + wn * 64 + nf * 8 + qc;
            atomicMax(&g_cmax[col],     enc_f(m0));
            atomicMax(&g_cmax[col + 1], enc_f(m1));
        }
    }
}

// ===========================================================================
// K3: stats — stage 64x128 block in smem (~41KB -> 5 CTA/SM), then
// register-accumulated row pass (rank counts + row sumexp, 64 rows x 4 segs)
// and col pass (col sumexp, 128 cols x 2 row-halves).
__global__ __launch_bounds__(256)
void stats_kernel() {
    __shared__ float tile[64 * SPAD];       // 33792 B
    __shared__ float sp[64][4];
    __shared__ float srm[64], sthr[64];
    __shared__ int   scnt4[4][64][4];       // per-seg rank counts
    __shared__ float srs4[4][64];           // per-seg row sumexp
    __shared__ float scs2[2][128];

    const int tid = threadIdx.x;
    const int ct = blockIdx.x, rt = blockIdx.y;
    const int c0 = ct * BN, r0 = rt * 64;

    // stage block (coalesced float4): 64 rows x 128 cols = 2048 float4
    #pragma unroll
    for (int i = 0; i < 8; i++) {
        int idx = i * 256 + tid;
        int r = idx >> 5, c4 = idx & 31;
        float4 v = *reinterpret_cast<const float4*>(
            g_S + (size_t)(r0 + r) * NT + c0 + c4 * 4);
        *reinterpret_cast<float4*>(&tile[r * SPAD + c4 * 4]) = v;
    }
    if (tid < 64) {
        int gr = r0 + tid;
        float rm = dec_f(g_rmax[gr]);
        srm[tid] = rm;
        sthr[tid] = rm - LSE_CUT;
        #pragma unroll
        for (int t = 0; t < 4; t++)
            sp[tid][t] = g_S[(size_t)gr * NT + gr * 4 + t];
    }
    __syncthreads();

    // ---- row pass: thread = (row, 32-col segment) ----
    {
        const int r = tid >> 2, seg = tid & 3;
        const float p0 = sp[r][0], p1 = sp[r][1], p2 = sp[r][2], p3 = sp[r][3];
        const float rm = srm[r], thr = sthr[r];
        int c0n = 0, c1n = 0, c2n = 0, c3n = 0;
        float rs = 0.f;
        const float* tp = &tile[r * SPAD + seg * 32];
        #pragma unroll 8
        for (int i = 0; i < 16; i++) {
            float2 xv = *reinterpret_cast<const float2*>(tp + i * 2);
            c0n += (xv.x > p0) + (xv.y > p0);
            c1n += (xv.x > p1) + (xv.y > p1);
            c2n += (xv.x > p2) + (xv.y > p2);
            c3n += (xv.x > p3) + (xv.y > p3);
            if (xv.x > thr) rs += expf(xv.x - rm);
            if (xv.y > thr) rs += expf(xv.y - rm);
        }
        scnt4[seg][r][0] = c0n; scnt4[seg][r][1] = c1n;
        scnt4[seg][r][2] = c2n; scnt4[seg][r][3] = c3n;
        srs4[seg][r] = rs;
    }

    // ---- col pass: thread = (col, 32-row half) ----
    {
        const int c = tid & 127, halfr = tid >> 7;
        const float cm = dec_f(g_cmax[c0 + c]);
        const float cthr = cm - LSE_CUT;
        float cs = 0.f;
        const float* tp = &tile[(halfr * 32) * SPAD + c];
        #pragma unroll 8
        for (int r = 0; r < 32; r++) {
            float x = tp[r * SPAD];
            if (x > cthr) cs += expf(x - cm);
        }
        scs2[halfr][c] = cs;
    }
    __syncthreads();

    if (tid < 128)
        g_cpart[rt][c0 + tid] = scs2[0][tid] + scs2[1][tid];
    if (tid < 64) {
        #pragma unroll
        for (int t = 0; t < 4; t++) {
            int c = scnt4[0][tid][t] + scnt4[1][tid][t] +
                    scnt4[2][tid][t] + scnt4[3][tid][t];
            atomicAdd(&g_cnt[r0 + tid][t], c);
        }
        g_rspart[ct][r0 + tid] = srs4[0][tid] + srs4[1][tid] +
                                 srs4[2][tid] + srs4[3][tid];
    }
}

// ===========================================================================
// K4: per-row finalize
__global__ __launch_bounds__(256)
void rowfin_kernel() {
    int i = blockIdx.x * 256 + threadIdx.x;
    if (i >= N) return;

    float p[4];
    #pragma unroll
    for (int t = 0; t < 4; t++) p[t] = g_S[(size_t)i * NT + i * 4 + t];
    float rm = dec_f(g_rmax[i]);

    float rsum = 0.f;
    for (int ct = 0; ct < CTILE; ct++) rsum += g_rspart[ct][i];

    float pm = fmaxf(fmaxf(p[0], p[1]), fmaxf(p[2], p[3]));
    float nom = pm + logf(expf(p[0] - pm) + expf(p[1] - pm) +
                          expf(p[2] - pm) + expf(p[3] - pm));

    float cmv[4], M = rm;
    #pragma unroll
    for (int t = 0; t < 4; t++) {
        cmv[t] = dec_f(g_cmax[i * 4 + t]);
        M = fmaxf(M, cmv[t]);
    }
    float tot = rsum * expf(rm - M);
    #pragma unroll
    for (int t = 0; t < 4; t++) {
        float cs = 0.f;
        for (int rt = 0; rt < RT64; rt++) cs += g_cpart[rt][i * 4 + t];
        tot += cs * expf(cmv[t] - M);
    }
    float denom = M + logf(tot);

    float r1 = 0.f, r5 = 0.f, r10 = 0.f, ar = 0.f;
    #pragma unroll
    for (int t = 0; t < 4; t++) {
        int rk = g_cnt[i][t];
        r1  += (rk < 1);
        r5  += (rk < 5);
        r10 += (rk < 10);
        ar  += (float)rk;
    }
    g_rowout[i][0] = denom - nom;
    g_rowout[i][1] = r1  * 0.25f;
    g_rowout[i][2] = r5  * 0.25f;
    g_rowout[i][3] = r10 * 0.25f;
    g_rowout[i][4] = ar  * 0.25f;
}

// ===========================================================================
// K5: deterministic means
__global__ __launch_bounds__(256)
void final_kernel(float* __restrict__ out) {
    __shared__ double sacc[5][256];
    int tid = threadIdx.x;
    double a[5] = {0, 0, 0, 0, 0};
    for (int i = tid; i < N; i += 256)
        #pragma unroll
        for (int q = 0; q < 5; q++) a[q] += (double)g_rowout[i][q];
    #pragma unroll
    for (int q = 0; q < 5; q++) sacc[q][tid] = a[q];
    __syncthreads();
    for (int off = 128; off > 0; off >>= 1) {
        if (tid < off)
            #pragma unroll
            for (int q = 0; q < 5; q++) sacc[q][tid] += sacc[q][tid + off];
        __syncthreads();
    }
    if (tid == 0)
        #pragma unroll
        for (int q = 0; q < 5; q++) out[q] = (float)(sacc[q][0] / (double)N);
}

// ===========================================================================
extern "C" void kernel_launch(void* const* d_in, const int* in_sizes, int n_in,
                              void* d_out, int out_size) {
    const float* v = (const float*)d_in[0];   // [4096, 256]
    const float* t = (const float*)d_in[1];   // [16384, 256]
    (void)in_sizes; (void)n_in; (void)out_size;

    static int attr_done = 0;
    if (!attr_done) {
        cudaFuncSetAttribute(gemm_mma, cudaFuncAttributeMaxDynamicSharedMemorySize, GEMM_SMEM);
        attr_done = 1;
    }

    init_kernel<<<(NT + 255) / 256, 256>>>();
    split_kernel<<<(NA + NB + 255) / 256, 256>>>(v, t);
    gemm_mma<<<dim3(CTILE, N / BM), 256, GEMM_SMEM>>>();
    stats_kernel<<<dim3(CTILE, RT64), 256>>>();
    rowfin_kernel<<<(N + 255) / 256, 256>>>();
    final_kernel<<<1, 256>>>((float*)d_out);
}

// round 16
// speedup vs baseline: 1.1663x; 1.0311x over previous
#include <cuda_runtime.h>
#include <cuda_bf16.h>
#include <math.h>
#include <cfloat>
#include <cstdint>

// ===========================================================================
// MIL-NCE head: s = (v @ t^T)/0.1, N=4096, T=4, D=256 (NT=16384)
// Outputs: [loss, recall1, recall5, recall10, avg_rank]
//
//  K0 init   : rmax/cmax <- -inf, cnt <- 0
//  K1 split  : fp32 -> 2x bf16 splits of v and t
//  K2 gemm   : mma.sync bf16 3-product GEMM, 64x128 CTA tile, 2 CTAs/SM
//              (96KB smem, <=128 regs), cp.async double-buffered;
//              S -> scratch + exact row/col maxes (deterministic atomicMax)
//  K3 stats  : smem-staged 64x128 block pass: rank counts, row/col sumexp
//  K4 rowfin : per-row LSE combine + metrics
//  K5 reduce : deterministic means
// ===========================================================================

namespace {
constexpr int N  = 4096;
constexpr int T  = 4;
constexpr int NT = 16384;
constexpr int D  = 256;
constexpr float SCALE   = 10.0f;
constexpr float LSE_CUT = 30.0f;

constexpr int BMG = 64;                     // gemm CTA tile rows
constexpr int BN  = 128;                    // gemm CTA tile cols
constexpr int KC = 64;                      // K chunk: 64 bf16 = 128B rows (SW128)
constexpr int NCHUNK = D / KC;              // 4
constexpr int CTILE = NT / BN;              // 128
constexpr int RTG   = N / BMG;              // 64 gemm row-tiles
constexpr int RT64  = N / 64;               // 64 stats row-tiles

constexpr int NA = N * D;
constexpr int NB = NT * D;

constexpr int ATILE_B  = BMG * KC * 2;      // 8192  bytes per A split tile
constexpr int BTILE_B  = BN  * KC * 2;      // 16384 bytes per B split tile
constexpr int STAGE_B  = 2 * ATILE_B + 2 * BTILE_B;  // 49152
constexpr int GEMM_SMEM = 2 * STAGE_B;      // 98304 (double buffer) -> 2 CTA/SM

constexpr int SPAD = 132;                   // stats tile row pitch (words)
}

// ------------------------- device scratch ---------------------------------
__device__ float          g_S[(size_t)N * NT];   // 256 MB
__device__ __nv_bfloat16  g_As[2][NA];
__device__ __nv_bfloat16  g_Bs[2][NB];
__device__ int            g_rmax[N];
__device__ int            g_cmax[NT];
__device__ int            g_cnt[N][T];
__device__ float          g_cpart[RT64][NT];     // col partial sumexp per 64-row tile
__device__ float          g_rspart[CTILE][N];    // row partial sumexp per col-tile
__device__ float          g_rowout[N][5];

// ------------------------- helpers ----------------------------------------
__device__ __forceinline__ int enc_f(float f) {
    int i = __float_as_int(f);
    return i >= 0 ? i : i ^ 0x7fffffff;
}
__device__ __forceinline__ float dec_f(int i) {
    return __int_as_float(i >= 0 ? i : i ^ 0x7fffffff);
}
__device__ __forceinline__ uint32_t smem_u32(const void* p) {
    uint32_t a;
    asm("{ .reg .u64 t; cvta.to.shared.u64 t, %1; cvt.u32.u64 %0, t; }" : "=r"(a) : "l"(p));
    return a;
}
__device__ __forceinline__ uint32_t sw128(uint32_t b) { return b ^ ((b >> 3) & 0x70); }

__device__ __forceinline__ void ldsm4(uint32_t* r, uint32_t addr) {
    asm volatile("ldmatrix.sync.aligned.m8n8.x4.shared.b16 {%0,%1,%2,%3}, [%4];"
        : "=r"(r[0]), "=r"(r[1]), "=r"(r[2]), "=r"(r[3]) : "r"(addr));
}
__device__ __forceinline__ void mma_bf16(float* d, const uint32_t* a, uint32_t b0, uint32_t b1) {
    asm volatile("mma.sync.aligned.m16n8k16.row.col.f32.bf16.bf16.f32 "
        "{%0,%1,%2,%3}, {%4,%5,%6,%7}, {%8,%9}, {%0,%1,%2,%3};"
        : "+f"(d[0]), "+f"(d[1]), "+f"(d[2]), "+f"(d[3])
        : "r"(a[0]), "r"(a[1]), "r"(a[2]), "r"(a[3]), "r"(b0), "r"(b1));
}
__device__ __forceinline__ void cp16(uint32_t dst, const void* src) {
    asm volatile("cp.async.cg.shared.global [%0], [%1], 16;" :: "r"(dst), "l"(src));
}
#define CP_COMMIT() asm volatile("cp.async.commit_group;" ::: "memory")
#define CP_WAIT(n)  asm volatile("cp.async.wait_group %0;" :: "n"(n) : "memory")

// ===========================================================================
// K0: init
__global__ void init_kernel() {
    int i = blockIdx.x * 256 + threadIdx.x;
    if (i < N)  g_rmax[i] = (int)0x80000000;
    if (i < NT) {
        g_cmax[i] = (int)0x80000000;
        g_cnt[i >> 2][i & 3] = 0;
    }
}

// ===========================================================================
// K1: 2-way bf16 split
__global__ __launch_bounds__(256)
void split_kernel(const float* __restrict__ v, const float* __restrict__ t) {
    int i = blockIdx.x * 256 + threadIdx.x;
    if (i >= NA + NB) return;
    float a = (i < NA) ? v[i] : t[i - NA];
    __nv_bfloat16 h0 = __float2bfloat16(a);
    float r1 = a - __bfloat162float(h0);
    __nv_bfloat16 h1 = __float2bfloat16(r1);
    if (i < NA) { g_As[0][i] = h0; g_As[1][i] = h1; }
    else { int j = i - NA; g_Bs[0][j] = h0; g_Bs[1][j] = h1; }
}

// ===========================================================================
// K2: HMMA GEMM, 64x128 CTA tile, 8 warps as 2(m) x 4(n), warp tile 32x32.
// 2 CTAs/SM: one CTA's epilogue overlaps the other's MMA stream.
__global__ __launch_bounds__(256, 2)
void gemm_mma() {
    extern __shared__ char smem[];
    const uint32_t sb = smem_u32(smem);
    const int tid = threadIdx.x, lane = tid & 31, wid = tid >> 5;
    const int wm = wid >> 2, wn = wid & 3;
    const int bn = blockIdx.x, bm = blockIdx.y;

    const int a_r    = lane & 15;
    const int a_koff = (lane >> 4) * 16;
    const int b_r    = (lane & 7) + ((lane & 16) >> 1);
    const int b_koff = (lane & 8) << 1;
    const uint32_t a_xm = (uint32_t)(a_r & 7) << 4;
    const uint32_t b_xm = (uint32_t)(b_r & 7) << 4;

    uint32_t a_rowb[2], b_rowb[2];
    #pragma unroll
    for (int mi = 0; mi < 2; mi++) a_rowb[mi] = (uint32_t)(wm * 32 + mi * 16 + a_r) * 128;
    #pragma unroll
    for (int p = 0; p < 2; p++)    b_rowb[p]  = (uint32_t)(wn * 32 + p * 16 + b_r) * 128;

    float acc[2][4][4];
    #pragma unroll
    for (int mi = 0; mi < 2; mi++)
        #pragma unroll
        for (int nf = 0; nf < 4; nf++)
            #pragma unroll
            for (int q = 0; q < 4; q++) acc[mi][nf][q] = 0.f;

    // stage layout: [A0 8K][A1 8K][B0 16K][B1 16K]
    auto prefetch = [&](int stage, int kc) {
        const int k0 = kc * KC;
        #pragma unroll
        for (int i = 0; i < 12; i++) {
            int g = i * 256 + tid;          // 0..3071 16B-chunks
            uint32_t dst;
            const __nv_bfloat16* src;
            if (g < 1024) {                 // A tiles: 512 chunks each
                int s = g >> 9, idx = g & 511;
                int r = idx >> 3, b = idx & 7;
                src = g_As[s] + (size_t)(bm * BMG + r) * D + k0 + b * 8;
                dst = sb + stage * STAGE_B + s * ATILE_B + sw128(r * 128 + b * 16);
            } else {                        // B tiles: 1024 chunks each
                int g2 = g - 1024;
                int s = g2 >> 10, idx = g2 & 1023;
                int r = idx >> 3, b = idx & 7;
                src = g_Bs[s] + (size_t)(bn * BN + r) * D + k0 + b * 8;
                dst = sb + stage * STAGE_B + 2 * ATILE_B + s * BTILE_B + sw128(r * 128 + b * 16);
            }
            cp16(dst, src);
        }
    };

    prefetch(0, 0);
    CP_COMMIT();

    for (int kc = 0; kc < NCHUNK; kc++) {
        if (kc < NCHUNK - 1) { prefetch((kc + 1) & 1, kc + 1); CP_COMMIT(); CP_WAIT(1); }
        else { CP_WAIT(0); }
        __syncthreads();

        const uint32_t base  = sb + (kc & 1) * STAGE_B;
        const uint32_t baseB = base + 2 * ATILE_B;
        #pragma unroll
        for (int k16 = 0; k16 < 4; k16++) {
            const uint32_t kb = k16 * 32;
            uint32_t af[2][2][4];   // [split][mi]
            #pragma unroll
            for (int s2 = 0; s2 < 2; s2++)
                #pragma unroll
                for (int mi = 0; mi < 2; mi++)
                    ldsm4(af[s2][mi], base + s2 * ATILE_B + a_rowb[mi] + ((kb + a_koff) ^ a_xm));
            uint32_t bf[2][2][4];   // [split][p]
            #pragma unroll
            for (int s2 = 0; s2 < 2; s2++)
                #pragma unroll
                for (int p = 0; p < 2; p++)
                    ldsm4(bf[s2][p], baseB + s2 * BTILE_B + b_rowb[p] + ((kb + b_koff) ^ b_xm));

            #pragma unroll
            for (int mi = 0; mi < 2; mi++)
                #pragma unroll
                for (int nf = 0; nf < 4; nf++) {
                    const uint32_t* bp0 = &bf[0][nf >> 1][(nf & 1) * 2];
                    const uint32_t* bp1 = &bf[1][nf >> 1][(nf & 1) * 2];
                    mma_bf16(acc[mi][nf], af[0][mi], bp0[0], bp0[1]);
                    mma_bf16(acc[mi][nf], af[0][mi], bp1[0], bp1[1]);
                    mma_bf16(acc[mi][nf], af[1][mi], bp0[0], bp0[1]);
                }
        }
        __syncthreads();
    }

    // ---- epilogue: scale, store S, exact row/col maxes ----
    #pragma unroll
    for (int mi = 0; mi < 2; mi++)
        #pragma unroll
        for (int nf = 0; nf < 4; nf++)
            #pragma unroll
            for (int q = 0; q < 4; q++) acc[mi][nf][q] *= SCALE;

    const int qr = lane >> 2;
    const int qc = (lane & 3) * 2;

    #pragma unroll
    for (int mi = 0; mi < 2; mi++)
        #pragma unroll
        for (int h = 0; h < 2; h++) {
            int row = bm * BMG + wm * 32 + mi * 16 + h * 8 + qr;
            float* dst = g_S + (size_t)row * NT + (size_t)bn * BN + wn * 32 + qc;
            #pragma unroll
            for (int nf = 0; nf < 4; nf++)
                *reinterpret_cast<float2*>(dst + nf * 8) =
                    make_float2(acc[mi][nf][2 * h], acc[mi][nf][2 * h + 1]);
        }

    #pragma unroll
    for (int mi = 0; mi < 2; mi++)
        #pragma unroll
        for (int h = 0; h < 2; h++) {
            float m = -FLT_MAX;
            #pragma unroll
            for (int nf = 0; nf < 4; nf++)
                m = fmaxf(m, fmaxf(acc[mi][nf][2 * h], acc[mi][nf][2 * h + 1]));
            m = fmaxf(m, __shfl_xor_sync(0xffffffffu, m, 1));
            m = fmaxf(m, __shfl_xor_sync(0xffffffffu, m, 2));
            if ((lane & 3) == 0)
                atomicMax(&g_rmax[bm * BMG + wm * 32 + mi * 16 + h * 8 + qr], enc_f(m));
        }

    #pragma unroll
    for (int nf = 0; nf < 4; nf++) {
        float m0 = -FLT_MAX, m1 = -FLT_MAX;
        #pragma unroll
        for (int mi = 0; mi < 2; mi++) {
            m0 = fmaxf(m0, fmaxf(acc[mi][nf][0], acc[mi][nf][2]));
            m1 = fmaxf(m1, fmaxf(acc[mi][nf][1], acc[mi][nf][3]));
        }
        #pragma unroll
        for (int off = 4; off < 32; off <<= 1) {
            m0 = fmaxf(m0, __shfl_xor_sync(0xffffffffu, m0, off));
            m1 = fmaxf(m1, __shfl_xor_sync(0xffffffffu, m1, off));
        }
        if (lane < 4) {
            int col = bn * BN + wn * 32 + nf * 8 + qc;
            atomicMax(&g_cmax[col],     enc_f(m0));
            atomicMax(&g_cmax[col + 1], enc_f(m1));
        }
    }
}

// ===========================================================================
// K3: stats — stage 64x128 block in smem, row pass (rank counts + row
// sumexp) and col pass (col sumexp), register-accumulated. (R13-identical)
__global__ __launch_bounds__(256)
void stats_kernel() {
    __shared__ float tile[64 * SPAD];
    __shared__ float sp[64][4];
    __shared__ float srm[64], sthr[64];
    __shared__ int   scnt4[4][64][4];
    __shared__ float srs4[4][64];
    __shared__ float scs2[2][128];

    const int tid = threadIdx.x;
    const int ct = blockIdx.x, rt = blockIdx.y;
    const int c0 = ct * BN, r0 = rt * 64;

    #pragma unroll
    for (int i = 0; i < 8; i++) {
        int idx = i * 256 + tid;
        int r = idx >> 5, c4 = idx & 31;
        float4 v = *reinterpret_cast<const float4*>(
            g_S + (size_t)(r0 + r) * NT + c0 + c4 * 4);
        *reinterpret_cast<float4*>(&tile[r * SPAD + c4 * 4]) = v;
    }
    if (tid < 64) {
        int gr = r0 + tid;
        float rm = dec_f(g_rmax[gr]);
        srm[tid] = rm;
        sthr[tid] = rm - LSE_CUT;
        #pragma unroll
        for (int t = 0; t < 4; t++)
            sp[tid][t] = g_S[(size_t)gr * NT + gr * 4 + t];
    }
    __syncthreads();

    {
        const int r = tid >> 2, seg = tid & 3;
        const float p0 = sp[r][0], p1 = sp[r][1], p2 = sp[r][2], p3 = sp[r][3];
        const float rm = srm[r], thr = sthr[r];
        int c0n = 0, c1n = 0, c2n = 0, c3n = 0;
        float rs = 0.f;
        const float* tp = &tile[r * SPAD + seg * 32];
        #pragma unroll 8
        for (int i = 0; i < 16; i++) {
            float2 xv = *reinterpret_cast<const float2*>(tp + i * 2);
            c0n += (xv.x > p0) + (xv.y > p0);
            c1n += (xv.x > p1) + (xv.y > p1);
            c2n += (xv.x > p2) + (xv.y > p2);
            c3n += (xv.x > p3) + (xv.y > p3);
            if (xv.x > thr) rs += expf(xv.x - rm);
            if (xv.y > thr) rs += expf(xv.y - rm);
        }
        scnt4[seg][r][0] = c0n; scnt4[seg][r][1] = c1n;
        scnt4[seg][r][2] = c2n; scnt4[seg][r][3] = c3n;
        srs4[seg][r] = rs;
    }

    {
        const int c = tid & 127, halfr = tid >> 7;
        const float cm = dec_f(g_cmax[c0 + c]);
        const float cthr = cm - LSE_CUT;
        float cs = 0.f;
        const float* tp = &tile[(halfr * 32) * SPAD + c];
        #pragma unroll 8
        for (int r = 0; r < 32; r++) {
            float x = tp[r * SPAD];
            if (x > cthr) cs += expf(x - cm);
        }
        scs2[halfr][c] = cs;
    }
    __syncthreads();

    if (tid < 128)
        g_cpart[rt][c0 + tid] = scs2[0][tid] + scs2[1][tid];
    if (tid < 64) {
        #pragma unroll
        for (int t = 0; t < 4; t++) {
            int c = scnt4[0][tid][t] + scnt4[1][tid][t] +
                    scnt4[2][tid][t] + scnt4[3][tid][t];
            atomicAdd(&g_cnt[r0 + tid][t], c);
        }
        g_rspart[ct][r0 + tid] = srs4[0][tid] + srs4[1][tid] +
                                 srs4[2][tid] + srs4[3][tid];
    }
}

// ===========================================================================
// K4: per-row finalize
__global__ __launch_bounds__(256)
void rowfin_kernel() {
    int i = blockIdx.x * 256 + threadIdx.x;
    if (i >= N) return;

    float p[4];
    #pragma unroll
    for (int t = 0; t < 4; t++) p[t] = g_S[(size_t)i * NT + i * 4 + t];
    float rm = dec_f(g_rmax[i]);

    float rsum = 0.f;
    for (int ct = 0; ct < CTILE; ct++) rsum += g_rspart[ct][i];

    float pm = fmaxf(fmaxf(p[0], p[1]), fmaxf(p[2], p[3]));
    float nom = pm + logf(expf(p[0] - pm) + expf(p[1] - pm) +
                          expf(p[2] - pm) + expf(p[3] - pm));

    float cmv[4], M = rm;
    #pragma unroll
    for (int t = 0; t < 4; t++) {
        cmv[t] = dec_f(g_cmax[i * 4 + t]);
        M = fmaxf(M, cmv[t]);
    }
    float tot = rsum * expf(rm - M);
    #pragma unroll
    for (int t = 0; t < 4; t++) {
        float cs = 0.f;
        for (int rt = 0; rt < RT64; rt++) cs += g_cpart[rt][i * 4 + t];
        tot += cs * expf(cmv[t] - M);
    }
    float denom = M + logf(tot);

    float r1 = 0.f, r5 = 0.f, r10 = 0.f, ar = 0.f;
    #pragma unroll
    for (int t = 0; t < 4; t++) {
        int rk = g_cnt[i][t];
        r1  += (rk < 1);
        r5  += (rk < 5);
        r10 += (rk < 10);
        ar  += (float)rk;
    }
    g_rowout[i][0] = denom - nom;
    g_rowout[i][1] = r1  * 0.25f;
    g_rowout[i][2] = r5  * 0.25f;
    g_rowout[i][3] = r10 * 0.25f;
    g_rowout[i][4] = ar  * 0.25f;
}

// ===========================================================================
// K5: deterministic means
__global__ __launch_bounds__(256)
void final_kernel(float* __restrict__ out) {
    __shared__ double sacc[5][256];
    int tid = threadIdx.x;
    double a[5] = {0, 0, 0, 0, 0};
    for (int i = tid; i < N; i += 256)
        #pragma unroll
        for (int q = 0; q < 5; q++) a[q] += (double)g_rowout[i][q];
    #pragma unroll
    for (int q = 0; q < 5; q++) sacc[q][tid] = a[q];
    __syncthreads();
    for (int off = 128; off > 0; off >>= 1) {
        if (tid < off)
            #pragma unroll
            for (int q = 0; q < 5; q++) sacc[q][tid] += sacc[q][tid + off];
        __syncthreads();
    }
    if (tid == 0)
        #pragma unroll
        for (int q = 0; q < 5; q++) out[q] = (float)(sacc[q][0] / (double)N);
}

// ===========================================================================
extern "C" void kernel_launch(void* const* d_in, const int* in_sizes, int n_in,
                              void* d_out, int out_size) {
    const float* v = (const float*)d_in[0];   // [4096, 256]
    const float* t = (const float*)d_in[1];   // [16384, 256]
    (void)in_sizes; (void)n_in; (void)out_size;

    static int attr_done = 0;
    if (!attr_done) {
        cudaFuncSetAttribute(gemm_mma, cudaFuncAttributeMaxDynamicSharedMemorySize, GEMM_SMEM);
        attr_done = 1;
    }

    init_kernel<<<(NT + 255) / 256, 256>>>();
    split_kernel<<<(NA + NB + 255) / 256, 256>>>(v, t);
    gemm_mma<<<dim3(CTILE, RTG), 256, GEMM_SMEM>>>();
    stats_kernel<<<dim3(CTILE, RT64), 256>>>();
    rowfin_kernel<<<(N + 255) / 256, 256>>>();
    final_kernel<<<1, 256>>>((float*)d_out);
}